// round 9
// baseline (speedup 1.0000x reference)
#include <cuda_runtime.h>

// EEG_SimpleLSM: 3-layer LIF winner-take-all liquid state machine.
// x: [256, 32, 4000] f32, W1: [64,32], W2: [128,64]. Output: exp(pre_v2@T-1) [256,128].
//
// ROUND 9: full stage decoupling via chunked token streams. R8 showed warp A
// (L0+L1 fused) latency-exposed at ~122 cyc/step: the within-step chain
// v0->REDUX->idx0->LDG->REDUX->token only overlaps ~1.2 steps. Fix: run L0 a
// full chunk AHEAD, materializing (s0,idx0) tokens in smem, so L1's 80
// per-step chains become mutually independent (only the 24-cyc v1 recurrence
// is serial). Same trick already proven for L2 in R7.
//
// Per sample (2 samples/CTA, 128 thr, grid 128, one warp per SMSP):
//   Warp B: L0 chunk c (producer) + L2 neurons 0..95 chunk c-2   (~44 instr/step)
//   Warp A: L1 chunk c-1 (consumer/producer) + L2 neurons 96..127 (~42 instr/step)
// Double-buffered token streams, 52 __syncthreads total.
//   s0tok buf[c&1] written by B at iter c, read by A at iter c+1.
//   s1tok buf[(c-1)&1] written by A at iter c, read by both at iter c+1
//   (L2 chunk c-2 reads buf[c&1]) -- disjoint parities each iteration.
// All stage arithmetic bit-identical to R3/R7/R8 (Markstein const division,
// REDUX max + REDUX min first-index tie-break) -> rel_err must remain
// exactly 4.882994e-08. __launch_bounds__(128,1) keeps the register budget.

#define NB    256
#define NCH   32
#define NT    4000
#define CHUNK 80
#define NCHK  (NT / CHUNK)     // 50
#define NBLK8 (NT / 8)         // 500

__device__ __align__(16) float g_W1T[32 * 64];   // W1T[c][j] = W1[j][c]
__device__ __align__(16) float g_W2T[64 * 128];  // W2T[c][j] = W2[j][c]

__global__ void prep_kernel(const float* __restrict__ W1, const float* __restrict__ W2) {
    int tid = blockIdx.x * blockDim.x + threadIdx.x;
    int nthr = blockDim.x * gridDim.x;
    for (int i = tid; i < 64 * 32; i += nthr) {
        int r = i >> 5, c = i & 31;
        g_W1T[c * 64 + r] = W1[i];
    }
    for (int i = tid; i < 128 * 64; i += nthr) {
        int r = i >> 6, c = i & 63;
        g_W2T[c * 128 + r] = W2[i];
    }
}

// Correctly-rounded division by constant c (rc = RN(1/c)), Markstein sequence.
__device__ __forceinline__ float divc(float v, float c, float rc) {
    float q = v * rc;
    float r = __fmaf_rn(-c, q, v);
    return __fmaf_rn(r, rc, q);
}

// Monotone key: strictly order-preserving float -> unsigned mapping.
__device__ __forceinline__ unsigned fkey(float v) {
    unsigned b = __float_as_uint(v);
    return b ^ ((unsigned)((int)b >> 31) | 0x80000000u);
}

// key(1.5f): 0x3FC00000 -> 0xBFC00000 ; key(1.2f): 0x3F99999A -> 0xBF99999A
#define KEY_VTH0 0xBFC00000u
#define KEY_VTH1 0xBF99999Au

__device__ __forceinline__ unsigned smem_u32(const void* p) {
    unsigned r;
    asm("{ .reg .u64 t; cvta.to.shared.u64 t, %1; cvt.u32.u64 %0, t; }"
        : "=r"(r) : "l"(p));
    return r;
}

// Predicated single-lane shared store (no BSSY/BSYNC).
__device__ __forceinline__ void sts_lane0(int lane, unsigned addr, unsigned val) {
    asm volatile(
        "{\n\t"
        ".reg .pred p;\n\t"
        "setp.eq.s32 p, %0, 0;\n\t"
        "@p st.shared.u32 [%1], %2;\n\t"
        "}"
        :: "r"(lane), "r"(addr), "r"(val) : "memory");
}

__global__ void __launch_bounds__(128, 1)
lsm_kernel(const float* __restrict__ x, float* __restrict__ out) {
    // token streams: [sample][buffer][step-in-chunk]
    __shared__ unsigned s0tok[2][2][CHUNK];
    __shared__ unsigned s1tok[2][2][CHUNK];

    const int tid  = threadIdx.x;
    const int lane = tid & 31;
    const int warp = tid >> 5;
    const int samp = warp & 1;
    const int roleB = (warp >= 2);      // B = L0 producer + L2[0:96); A = L1 + L2[96:128)
    const int b    = (blockIdx.x << 1) + samp;

    const float RCT = 1.0f / 80000.0f;

    // --- B state ---
    float v0 = 0.0f;
    float v2x = 0.0f, v2y = 0.0f, v2z = 0.0f;   // neurons 2l, 2l+1, 64+l
    float pcx = 0.0f, pcy = 0.0f, pcz = 0.0f;
    float4 c0, c1;
    int gblk = 0;
    // --- A state ---
    float v1a = 0.0f, v1b = 0.0f;
    float v2w = 0.0f, pcw = 0.0f;               // neuron 96+l

    const float4* xp  = reinterpret_cast<const float4*>(x + (size_t)b * (NCH * NT) + lane * NT);
    const float2* w1p = reinterpret_cast<const float2*>(g_W1T);
    const float*  w2p = g_W2T;

    if (roleB) { c0 = __ldg(xp); c1 = __ldg(xp + 1); }

    for (int c = 0; c <= NCHK + 1; ++c) {
        if (roleB) {
            // ---- B: L0 chunk c (produce s0 tokens) ----
            if (c < NCHK) {
                unsigned tb = smem_u32(&s0tok[samp][c & 1][0]);
                for (int k = 0; k < CHUNK / 8; ++k) {
                    int nb = (gblk + 1 < NBLK8) ? (gblk + 1) * 2 : 0;
                    float4 n0 = __ldg(xp + nb);
                    float4 n1 = __ldg(xp + nb + 1);
                    float xs[8] = {c0.x, c0.y, c0.z, c0.w, c1.x, c1.y, c1.z, c1.w};
#pragma unroll
                    for (int j = 0; j < 8; ++j) {
                        float d0  = divc(v0, 3.0f, 1.0f / 3.0f);
                        float ch0 = (v0 + xs[j]) - d0;
                        unsigned k0   = fkey(ch0);
                        unsigned m0   = __reduce_max_sync(0xFFFFFFFFu, k0);
                        unsigned cand = (k0 == m0) ? (unsigned)lane : 32u;
                        unsigned idx0 = __reduce_min_sync(0xFFFFFFFFu, cand);
                        unsigned tok  = idx0 | ((m0 >= KEY_VTH0) ? 0x80000000u : 0u);
                        sts_lane0(lane, tb + (unsigned)((k * 8 + j) * 4), tok);
                        v0 = (ch0 >= 1.5f) ? 0.0f : ch0;
                    }
                    c0 = n0; c1 = n1; ++gblk;
                }
            }
            // ---- B: L2 neurons [0,96) chunk c-2 ----
            if (c >= 2) {
                const unsigned* sb = &s1tok[samp][c & 1][0];
#pragma unroll 4
                for (int j = 0; j < CHUNK; ++j) {
                    unsigned tok  = sb[j];
                    unsigned idx1 = tok & 0x7FFFFFFFu;
                    float s1 = (tok & 0x80000000u) ? 1.0f : 0.0f;
                    float2 wlo = __ldg(reinterpret_cast<const float2*>(w2p) + (idx1 << 6) + lane); // n 2l,2l+1
                    float  wmd = __ldg(w2p + (idx1 << 7) + 64 + lane);                             // n 64+l
                    float dx = divc(v2x, 80000.0f, RCT);
                    float dy = divc(v2y, 80000.0f, RCT);
                    float dz = divc(v2z, 80000.0f, RCT);
                    pcx = __fmaf_rn(wlo.x, s1, v2x) - dx;
                    pcy = __fmaf_rn(wlo.y, s1, v2y) - dy;
                    pcz = __fmaf_rn(wmd,   s1, v2z) - dz;
                    v2x = (pcx >= 1.2f) ? 0.0f : pcx;
                    v2y = (pcy >= 1.2f) ? 0.0f : pcy;
                    v2z = (pcz >= 1.2f) ? 0.0f : pcz;
                }
            }
        } else {
            // ---- A: L1 chunk c-1 (consume s0 tokens, produce s1 tokens) ----
            if (c >= 1 && c <= NCHK) {
                const unsigned* sb = &s0tok[samp][(c - 1) & 1][0];
                unsigned tb = smem_u32(&s1tok[samp][(c - 1) & 1][0]);
#pragma unroll 8
                for (int j = 0; j < CHUNK; ++j) {
                    unsigned tok0 = sb[j];
                    unsigned idx0 = tok0 & 0x7FFFFFFFu;
                    float s0 = (tok0 & 0x80000000u) ? 1.0f : 0.0f;
                    float2 w1 = __ldg(w1p + (idx0 << 5) + lane);   // W1T[idx0][2l..2l+1]
                    float d1a = divc(v1a, 80000.0f, RCT);
                    float d1b = divc(v1b, 80000.0f, RCT);
                    float cha = __fmaf_rn(w1.x, s0, v1a) - d1a;    // exact: s0 in {0,1}
                    float chb = __fmaf_rn(w1.y, s0, v1b) - d1b;
                    unsigned ka = fkey(cha);
                    unsigned kb = fkey(chb);
                    bool bw = kb > ka;
                    unsigned lk = bw ? kb : ka;
                    unsigned li = 2u * (unsigned)lane + (bw ? 1u : 0u);
                    unsigned m1   = __reduce_max_sync(0xFFFFFFFFu, lk);
                    unsigned cand = (lk == m1) ? li : 64u;
                    unsigned idx1 = __reduce_min_sync(0xFFFFFFFFu, cand);
                    unsigned tok1 = idx1 | ((m1 >= KEY_VTH1) ? 0x80000000u : 0u);
                    sts_lane0(lane, tb + (unsigned)(j * 4), tok1);
                    v1a = (cha >= 1.2f) ? 0.0f : cha;
                    v1b = (chb >= 1.2f) ? 0.0f : chb;
                }
            }
            // ---- A: L2 neurons [96,128) chunk c-2 ----
            if (c >= 2) {
                const unsigned* sb = &s1tok[samp][c & 1][0];
#pragma unroll 8
                for (int j = 0; j < CHUNK; ++j) {
                    unsigned tok  = sb[j];
                    unsigned idx1 = tok & 0x7FFFFFFFu;
                    float s1 = (tok & 0x80000000u) ? 1.0f : 0.0f;
                    float whi = __ldg(w2p + (idx1 << 7) + 96 + lane);  // n 96+l
                    float dw = divc(v2w, 80000.0f, RCT);
                    pcw = __fmaf_rn(whi, s1, v2w) - dw;
                    v2w = (pcw >= 1.2f) ? 0.0f : pcw;
                }
            }
        }
        __syncthreads();
    }

    // Output: liquid state = exp(pre-reset v2 at step NT-1). Disjoint ranges.
    float* ob = out + (size_t)b * 128;
    if (roleB) {
        float2 o2; o2.x = expf(pcx); o2.y = expf(pcy);
        reinterpret_cast<float2*>(ob)[lane] = o2;        // neurons 2l, 2l+1
        ob[64 + lane] = expf(pcz);                       // neuron 64+l
    } else {
        ob[96 + lane] = expf(pcw);                       // neuron 96+l
    }
}

extern "C" void kernel_launch(void* const* d_in, const int* in_sizes, int n_in,
                              void* d_out, int out_size) {
    const float* x  = (const float*)d_in[0];
    const float* W1 = (const float*)d_in[1];
    const float* W2 = (const float*)d_in[2];
    float* out = (float*)d_out;

    prep_kernel<<<1, 256>>>(W1, W2);
    lsm_kernel<<<NB / 2, 128>>>(x, out);
}

// round 10
// speedup vs baseline: 1.1035x; 1.1035x over previous
#include <cuda_runtime.h>

// EEG_SimpleLSM: 3-layer LIF winner-take-all liquid state machine.
// x: [256, 32, 4000] f32, W1: [64,32], W2: [128,64]. Output: exp(pre_v2@T-1) [256,128].
//
// ROUND 10 = ROUND 9 structure + the real fix. R9's consumer loops serialized
// (~185 cyc/step) because sts_lane0 carried an asm "memory" clobber: the
// compiler could not hoist step j+1's token LDS above step j's token STS, so
// every L1 step ran its full LDS->LDG->REDUX->REDUX->STS chain (~125 cyc)
// back-to-back. (Same fence was in R7/R8 -- explains their ~120 cyc/step and
// why the BSSY fix was a no-op.) Changes:
//   1. sts_lane0 loses the "memory" clobber (still volatile: not deletable,
//      not movable across __syncthreads; s0-read/s1-write buffers disjoint).
//   2. Consumer loops prefetch tokens in groups of 8 into registers BEFORE
//      the 8-step compute/store group -- loads batched ahead in source order.
// Dataflow per sample (2 samples/CTA, 128 thr, grid 128, 1 warp/SMSP):
//   Warp B: L0 chunk c (producer) + L2 neurons [0,96) chunk c-2
//   Warp A: L1 chunk c-1 (consumes s0 toks, produces s1 toks) + L2 [96,128)
// Double-buffered 80-step token streams, 52 __syncthreads total.
// All stage arithmetic bit-identical to R3..R9 -> rel_err must remain
// exactly 4.882994e-08. __launch_bounds__(128,1) keeps the register budget.

#define NB    256
#define NCH   32
#define NT    4000
#define CHUNK 80
#define NCHK  (NT / CHUNK)     // 50
#define NBLK8 (NT / 8)         // 500

__device__ __align__(16) float g_W1T[32 * 64];   // W1T[c][j] = W1[j][c]
__device__ __align__(16) float g_W2T[64 * 128];  // W2T[c][j] = W2[j][c]

__global__ void prep_kernel(const float* __restrict__ W1, const float* __restrict__ W2) {
    int tid = blockIdx.x * blockDim.x + threadIdx.x;
    int nthr = blockDim.x * gridDim.x;
    for (int i = tid; i < 64 * 32; i += nthr) {
        int r = i >> 5, c = i & 31;
        g_W1T[c * 64 + r] = W1[i];
    }
    for (int i = tid; i < 128 * 64; i += nthr) {
        int r = i >> 6, c = i & 63;
        g_W2T[c * 128 + r] = W2[i];
    }
}

// Correctly-rounded division by constant c (rc = RN(1/c)), Markstein sequence.
__device__ __forceinline__ float divc(float v, float c, float rc) {
    float q = v * rc;
    float r = __fmaf_rn(-c, q, v);
    return __fmaf_rn(r, rc, q);
}

// Monotone key: strictly order-preserving float -> unsigned mapping.
__device__ __forceinline__ unsigned fkey(float v) {
    unsigned b = __float_as_uint(v);
    return b ^ ((unsigned)((int)b >> 31) | 0x80000000u);
}

// key(1.5f): 0x3FC00000 -> 0xBFC00000 ; key(1.2f): 0x3F99999A -> 0xBF99999A
#define KEY_VTH0 0xBFC00000u
#define KEY_VTH1 0xBF99999Au

__device__ __forceinline__ unsigned smem_u32(const void* p) {
    unsigned r;
    asm("{ .reg .u64 t; cvta.to.shared.u64 t, %1; cvt.u32.u64 %0, t; }"
        : "=r"(r) : "l"(p));
    return r;
}

// Predicated single-lane shared store. volatile (not deletable / not movable
// across barriers) but NO "memory" clobber: unrelated loads may be scheduled
// around it. That clobber was the R7-R9 serialization fence.
__device__ __forceinline__ void sts_lane0(int lane, unsigned addr, unsigned val) {
    asm volatile(
        "{\n\t"
        ".reg .pred p;\n\t"
        "setp.eq.s32 p, %0, 0;\n\t"
        "@p st.shared.u32 [%1], %2;\n\t"
        "}"
        :: "r"(lane), "r"(addr), "r"(val));
}

__global__ void __launch_bounds__(128, 1)
lsm_kernel(const float* __restrict__ x, float* __restrict__ out) {
    // token streams: [sample][buffer][step-in-chunk]
    __shared__ unsigned s0tok[2][2][CHUNK];
    __shared__ unsigned s1tok[2][2][CHUNK];

    const int tid  = threadIdx.x;
    const int lane = tid & 31;
    const int warp = tid >> 5;
    const int samp = warp & 1;
    const int roleB = (warp >= 2);      // B = L0 producer + L2[0:96); A = L1 + L2[96:128)
    const int b    = (blockIdx.x << 1) + samp;

    const float RCT = 1.0f / 80000.0f;

    // --- B state ---
    float v0 = 0.0f;
    float v2x = 0.0f, v2y = 0.0f, v2z = 0.0f;   // neurons 2l, 2l+1, 64+l
    float pcx = 0.0f, pcy = 0.0f, pcz = 0.0f;
    float4 c0, c1;
    int gblk = 0;
    // --- A state ---
    float v1a = 0.0f, v1b = 0.0f;
    float v2w = 0.0f, pcw = 0.0f;               // neuron 96+l

    const float4* xp  = reinterpret_cast<const float4*>(x + (size_t)b * (NCH * NT) + lane * NT);
    const float2* w1p = reinterpret_cast<const float2*>(g_W1T);
    const float*  w2p = g_W2T;

    if (roleB) { c0 = __ldg(xp); c1 = __ldg(xp + 1); }

    for (int c = 0; c <= NCHK + 1; ++c) {
        if (roleB) {
            // ---- B: L0 chunk c (produce s0 tokens) ----
            if (c < NCHK) {
                unsigned tb = smem_u32(&s0tok[samp][c & 1][0]);
                for (int k = 0; k < CHUNK / 8; ++k) {
                    int nb = (gblk + 1 < NBLK8) ? (gblk + 1) * 2 : 0;
                    float4 n0 = __ldg(xp + nb);
                    float4 n1 = __ldg(xp + nb + 1);
                    float xs[8] = {c0.x, c0.y, c0.z, c0.w, c1.x, c1.y, c1.z, c1.w};
#pragma unroll
                    for (int j = 0; j < 8; ++j) {
                        float d0  = divc(v0, 3.0f, 1.0f / 3.0f);
                        float ch0 = (v0 + xs[j]) - d0;
                        unsigned k0   = fkey(ch0);
                        unsigned m0   = __reduce_max_sync(0xFFFFFFFFu, k0);
                        unsigned cand = (k0 == m0) ? (unsigned)lane : 32u;
                        unsigned idx0 = __reduce_min_sync(0xFFFFFFFFu, cand);
                        unsigned tok  = idx0 | ((m0 >= KEY_VTH0) ? 0x80000000u : 0u);
                        sts_lane0(lane, tb + (unsigned)((k * 8 + j) * 4), tok);
                        v0 = (ch0 >= 1.5f) ? 0.0f : ch0;
                    }
                    c0 = n0; c1 = n1; ++gblk;
                }
            }
            // ---- B: L2 neurons [0,96) chunk c-2 ----
            if (c >= 2) {
                const unsigned* sb = &s1tok[samp][c & 1][0];
                for (int k = 0; k < CHUNK / 8; ++k) {
                    unsigned toks[8];
#pragma unroll
                    for (int j = 0; j < 8; ++j) toks[j] = sb[k * 8 + j];
#pragma unroll
                    for (int j = 0; j < 8; ++j) {
                        unsigned idx1 = toks[j] & 0x7FFFFFFFu;
                        float s1 = (toks[j] & 0x80000000u) ? 1.0f : 0.0f;
                        float2 wlo = __ldg(reinterpret_cast<const float2*>(w2p) + (idx1 << 6) + lane);
                        float  wmd = __ldg(w2p + (idx1 << 7) + 64 + lane);
                        float dx = divc(v2x, 80000.0f, RCT);
                        float dy = divc(v2y, 80000.0f, RCT);
                        float dz = divc(v2z, 80000.0f, RCT);
                        pcx = __fmaf_rn(wlo.x, s1, v2x) - dx;
                        pcy = __fmaf_rn(wlo.y, s1, v2y) - dy;
                        pcz = __fmaf_rn(wmd,   s1, v2z) - dz;
                        v2x = (pcx >= 1.2f) ? 0.0f : pcx;
                        v2y = (pcy >= 1.2f) ? 0.0f : pcy;
                        v2z = (pcz >= 1.2f) ? 0.0f : pcz;
                    }
                }
            }
        } else {
            // ---- A: L1 chunk c-1 (consume s0 tokens, produce s1 tokens) ----
            if (c >= 1 && c <= NCHK) {
                const unsigned* sb = &s0tok[samp][(c - 1) & 1][0];
                unsigned tb = smem_u32(&s1tok[samp][(c - 1) & 1][0]);
                for (int k = 0; k < CHUNK / 8; ++k) {
                    unsigned toks[8];
#pragma unroll
                    for (int j = 0; j < 8; ++j) toks[j] = sb[k * 8 + j];
#pragma unroll
                    for (int j = 0; j < 8; ++j) {
                        unsigned idx0 = toks[j] & 0x7FFFFFFFu;
                        float s0 = (toks[j] & 0x80000000u) ? 1.0f : 0.0f;
                        float2 w1 = __ldg(w1p + (idx0 << 5) + lane);   // W1T[idx0][2l..2l+1]
                        float d1a = divc(v1a, 80000.0f, RCT);
                        float d1b = divc(v1b, 80000.0f, RCT);
                        float cha = __fmaf_rn(w1.x, s0, v1a) - d1a;    // exact: s0 in {0,1}
                        float chb = __fmaf_rn(w1.y, s0, v1b) - d1b;
                        unsigned ka = fkey(cha);
                        unsigned kb = fkey(chb);
                        bool bw = kb > ka;
                        unsigned lk = bw ? kb : ka;
                        unsigned li = 2u * (unsigned)lane + (bw ? 1u : 0u);
                        unsigned m1   = __reduce_max_sync(0xFFFFFFFFu, lk);
                        unsigned cand = (lk == m1) ? li : 64u;
                        unsigned idx1 = __reduce_min_sync(0xFFFFFFFFu, cand);
                        unsigned tok1 = idx1 | ((m1 >= KEY_VTH1) ? 0x80000000u : 0u);
                        sts_lane0(lane, tb + (unsigned)((k * 8 + j) * 4), tok1);
                        v1a = (cha >= 1.2f) ? 0.0f : cha;
                        v1b = (chb >= 1.2f) ? 0.0f : chb;
                    }
                }
            }
            // ---- A: L2 neurons [96,128) chunk c-2 ----
            if (c >= 2) {
                const unsigned* sb = &s1tok[samp][c & 1][0];
                for (int k = 0; k < CHUNK / 8; ++k) {
                    unsigned toks[8];
#pragma unroll
                    for (int j = 0; j < 8; ++j) toks[j] = sb[k * 8 + j];
#pragma unroll
                    for (int j = 0; j < 8; ++j) {
                        unsigned idx1 = toks[j] & 0x7FFFFFFFu;
                        float s1 = (toks[j] & 0x80000000u) ? 1.0f : 0.0f;
                        float whi = __ldg(w2p + (idx1 << 7) + 96 + lane);  // n 96+l
                        float dw = divc(v2w, 80000.0f, RCT);
                        pcw = __fmaf_rn(whi, s1, v2w) - dw;
                        v2w = (pcw >= 1.2f) ? 0.0f : pcw;
                    }
                }
            }
        }
        __syncthreads();
    }

    // Output: liquid state = exp(pre-reset v2 at step NT-1). Disjoint ranges.
    float* ob = out + (size_t)b * 128;
    if (roleB) {
        float2 o2; o2.x = expf(pcx); o2.y = expf(pcy);
        reinterpret_cast<float2*>(ob)[lane] = o2;        // neurons 2l, 2l+1
        ob[64 + lane] = expf(pcz);                       // neuron 64+l
    } else {
        ob[96 + lane] = expf(pcw);                       // neuron 96+l
    }
}

extern "C" void kernel_launch(void* const* d_in, const int* in_sizes, int n_in,
                              void* d_out, int out_size) {
    const float* x  = (const float*)d_in[0];
    const float* W1 = (const float*)d_in[1];
    const float* W2 = (const float*)d_in[2];
    float* out = (float*)d_out;

    prep_kernel<<<1, 256>>>(W1, W2);
    lsm_kernel<<<NB / 2, 128>>>(x, out);
}

// round 11
// speedup vs baseline: 1.1516x; 1.0436x over previous
#include <cuda_runtime.h>

// EEG_SimpleLSM: 3-layer LIF winner-take-all liquid state machine.
// x: [256, 32, 4000] f32, W1: [64,32], W2: [128,64]. Output: exp(pre_v2@T-1) [256,128].
//
// ROUND 11. Unifying model from rounds 1-10: warp-collective REDUX ops have
// ~32-cyc reciprocal throughput per warp; REDUX count per warp-step, not
// scalar instruction count, set every measured time (R7A: 4 REDUX ~122 cyc;
// R10: 2 REDUX/warp ~143 cyc incl. other work). So: keep R10's decoupled
// dataflow (argmaxes already split across warps) and halve collective
// pressure:
//   1. tie-break via BALLOT+FFS instead of second REDUX (VOTE is cheap pipe);
//      identical first-index semantics (lowest tied lane = lowest neuron;
//      within-lane pair tie picks even neuron since kb>ka is false on ties).
//   2. token stores: warp-uniform value -> ALL lanes store same value to same
//      smem address (HW: one write, no serialization) -- no asm, no predicate.
//   3. B's two L2 weight loads packed into one float4 (g_W2B); A's L2 quarter
//      reads g_W2A. prep kernel builds both layouts.
// Dataflow per sample (2 samples/CTA, 128 thr, grid 128, 1 warp/SMSP):
//   Warp B: L0 chunk c (produce s0 toks) + L2 neurons [0,96) chunk c-2
//   Warp A: L1 chunk c-1 (s0 toks -> s1 toks) + L2 neurons [96,128) chunk c-2
// Double-buffered 80-step token streams, 52 __syncthreads total.
// Charge/reset arithmetic bit-identical to R3..R10 (Markstein const division,
// fma gathers exact) -> rel_err must remain exactly 4.882994e-08.

#define NB    256
#define NCH   32
#define NT    4000
#define CHUNK 80
#define NCHK  (NT / CHUNK)     // 50
#define NBLK8 (NT / 8)         // 500

__device__ __align__(16) float  g_W1T[32 * 64];    // W1T[c][j] = W1[j][c]
__device__ __align__(16) float4 g_W2B[64 * 32];    // [idx1][lane] = (n2l, n2l+1, n64+l, 0)
__device__ __align__(16) float  g_W2A[64 * 32];    // [idx1][lane] = n96+l

__global__ void prep_kernel(const float* __restrict__ W1, const float* __restrict__ W2) {
    int tid = blockIdx.x * blockDim.x + threadIdx.x;
    int nthr = blockDim.x * gridDim.x;
    for (int i = tid; i < 64 * 32; i += nthr) {
        int r = i >> 5, c = i & 31;
        g_W1T[c * 64 + r] = W1[i];          // W1 is [64][32]
    }
    for (int i = tid; i < 64 * 32; i += nthr) {
        int c = i >> 5, l = i & 31;         // c = idx1 (W2 column), l = lane
        float4 v;
        v.x = W2[(2 * l)     * 64 + c];
        v.y = W2[(2 * l + 1) * 64 + c];
        v.z = W2[(64 + l)    * 64 + c];
        v.w = 0.0f;
        g_W2B[i] = v;
        g_W2A[i] = W2[(96 + l) * 64 + c];
    }
}

// Correctly-rounded division by constant c (rc = RN(1/c)), Markstein sequence.
__device__ __forceinline__ float divc(float v, float c, float rc) {
    float q = v * rc;
    float r = __fmaf_rn(-c, q, v);
    return __fmaf_rn(r, rc, q);
}

// Monotone key: strictly order-preserving float -> unsigned mapping.
__device__ __forceinline__ unsigned fkey(float v) {
    unsigned b = __float_as_uint(v);
    return b ^ ((unsigned)((int)b >> 31) | 0x80000000u);
}

// key(1.5f): 0x3FC00000 -> 0xBFC00000 ; key(1.2f): 0x3F99999A -> 0xBF99999A
#define KEY_VTH0 0xBFC00000u
#define KEY_VTH1 0xBF99999Au

__global__ void __launch_bounds__(128, 1)
lsm_kernel(const float* __restrict__ x, float* __restrict__ out) {
    // token streams: [sample][buffer][step-in-chunk]
    __shared__ unsigned s0tok[2][2][CHUNK];
    __shared__ unsigned s1tok[2][2][CHUNK];

    const int tid  = threadIdx.x;
    const int lane = tid & 31;
    const int warp = tid >> 5;
    const int samp = warp & 1;
    const int roleB = (warp >= 2);      // B = L0 producer + L2[0:96); A = L1 + L2[96:128)
    const int b    = (blockIdx.x << 1) + samp;

    const float RCT = 1.0f / 80000.0f;

    // --- B state ---
    float v0 = 0.0f;
    float v2x = 0.0f, v2y = 0.0f, v2z = 0.0f;   // neurons 2l, 2l+1, 64+l
    float pcx = 0.0f, pcy = 0.0f, pcz = 0.0f;
    float4 c0, c1;
    int gblk = 0;
    // --- A state ---
    float v1a = 0.0f, v1b = 0.0f;
    float v2w = 0.0f, pcw = 0.0f;               // neuron 96+l

    const float4* xp   = reinterpret_cast<const float4*>(x + (size_t)b * (NCH * NT) + lane * NT);
    const float2* w1p  = reinterpret_cast<const float2*>(g_W1T);
    const float4* w2bp = g_W2B;
    const float*  w2ap = g_W2A;

    if (roleB) { c0 = __ldg(xp); c1 = __ldg(xp + 1); }

    for (int c = 0; c <= NCHK + 1; ++c) {
        if (roleB) {
            // ---- B: L0 chunk c (produce s0 tokens) ----
            if (c < NCHK) {
                unsigned* tb = &s0tok[samp][c & 1][0];
                for (int k = 0; k < CHUNK / 8; ++k) {
                    int nb = (gblk + 1 < NBLK8) ? (gblk + 1) * 2 : 0;
                    float4 n0 = __ldg(xp + nb);
                    float4 n1 = __ldg(xp + nb + 1);
                    float xs[8] = {c0.x, c0.y, c0.z, c0.w, c1.x, c1.y, c1.z, c1.w};
#pragma unroll
                    for (int j = 0; j < 8; ++j) {
                        float d0  = divc(v0, 3.0f, 1.0f / 3.0f);
                        float ch0 = (v0 + xs[j]) - d0;
                        unsigned k0  = fkey(ch0);
                        unsigned m0  = __reduce_max_sync(0xFFFFFFFFu, k0);
                        unsigned bal = __ballot_sync(0xFFFFFFFFu, k0 == m0);
                        unsigned idx0 = (unsigned)__ffs(bal) - 1u;  // first-index tie-break
                        unsigned tok  = idx0 | ((m0 >= KEY_VTH0) ? 0x80000000u : 0u);
                        tb[k * 8 + j] = tok;   // warp-uniform: one HW write
                        v0 = (ch0 >= 1.5f) ? 0.0f : ch0;
                    }
                    c0 = n0; c1 = n1; ++gblk;
                }
            }
            // ---- B: L2 neurons [0,96) chunk c-2 ----
            if (c >= 2) {
                const unsigned* sb = &s1tok[samp][c & 1][0];
                for (int k = 0; k < CHUNK / 8; ++k) {
                    unsigned toks[8];
#pragma unroll
                    for (int j = 0; j < 8; ++j) toks[j] = sb[k * 8 + j];
#pragma unroll
                    for (int j = 0; j < 8; ++j) {
                        unsigned idx1 = toks[j] & 0x7FFFFFFFu;
                        float s1 = (toks[j] & 0x80000000u) ? 1.0f : 0.0f;
                        float4 w = __ldg(w2bp + (idx1 << 5) + lane);   // n 2l,2l+1,64+l
                        float dx = divc(v2x, 80000.0f, RCT);
                        float dy = divc(v2y, 80000.0f, RCT);
                        float dz = divc(v2z, 80000.0f, RCT);
                        pcx = __fmaf_rn(w.x, s1, v2x) - dx;
                        pcy = __fmaf_rn(w.y, s1, v2y) - dy;
                        pcz = __fmaf_rn(w.z, s1, v2z) - dz;
                        v2x = (pcx >= 1.2f) ? 0.0f : pcx;
                        v2y = (pcy >= 1.2f) ? 0.0f : pcy;
                        v2z = (pcz >= 1.2f) ? 0.0f : pcz;
                    }
                }
            }
        } else {
            // ---- A: L1 chunk c-1 (consume s0 tokens, produce s1 tokens) ----
            if (c >= 1 && c <= NCHK) {
                const unsigned* sb = &s0tok[samp][(c - 1) & 1][0];
                unsigned* tb = &s1tok[samp][(c - 1) & 1][0];
                for (int k = 0; k < CHUNK / 8; ++k) {
                    unsigned toks[8];
#pragma unroll
                    for (int j = 0; j < 8; ++j) toks[j] = sb[k * 8 + j];
#pragma unroll
                    for (int j = 0; j < 8; ++j) {
                        unsigned idx0 = toks[j] & 0x7FFFFFFFu;
                        float s0 = (toks[j] & 0x80000000u) ? 1.0f : 0.0f;
                        float2 w1 = __ldg(w1p + (idx0 << 5) + lane);   // W1T[idx0][2l..2l+1]
                        float d1a = divc(v1a, 80000.0f, RCT);
                        float d1b = divc(v1b, 80000.0f, RCT);
                        float cha = __fmaf_rn(w1.x, s0, v1a) - d1a;    // exact: s0 in {0,1}
                        float chb = __fmaf_rn(w1.y, s0, v1b) - d1b;
                        unsigned ka = fkey(cha);
                        unsigned kb = fkey(chb);
                        // pair tie-break ballot is independent of the REDUX
                        unsigned bwb = __ballot_sync(0xFFFFFFFFu, kb > ka);
                        unsigned lk  = (kb > ka) ? kb : ka;
                        unsigned m1  = __reduce_max_sync(0xFFFFFFFFu, lk);
                        unsigned bal = __ballot_sync(0xFFFFFFFFu, lk == m1);
                        unsigned wl  = (unsigned)__ffs(bal) - 1u;      // lowest tied lane
                        unsigned idx1 = 2u * wl + ((bwb >> wl) & 1u);
                        unsigned tok1 = idx1 | ((m1 >= KEY_VTH1) ? 0x80000000u : 0u);
                        tb[k * 8 + j] = tok1;  // warp-uniform: one HW write
                        v1a = (cha >= 1.2f) ? 0.0f : cha;
                        v1b = (chb >= 1.2f) ? 0.0f : chb;
                    }
                }
            }
            // ---- A: L2 neurons [96,128) chunk c-2 ----
            if (c >= 2) {
                const unsigned* sb = &s1tok[samp][c & 1][0];
                for (int k = 0; k < CHUNK / 8; ++k) {
                    unsigned toks[8];
#pragma unroll
                    for (int j = 0; j < 8; ++j) toks[j] = sb[k * 8 + j];
#pragma unroll
                    for (int j = 0; j < 8; ++j) {
                        unsigned idx1 = toks[j] & 0x7FFFFFFFu;
                        float s1 = (toks[j] & 0x80000000u) ? 1.0f : 0.0f;
                        float whi = __ldg(w2ap + (idx1 << 5) + lane);  // n 96+l
                        float dw = divc(v2w, 80000.0f, RCT);
                        pcw = __fmaf_rn(whi, s1, v2w) - dw;
                        v2w = (pcw >= 1.2f) ? 0.0f : pcw;
                    }
                }
            }
        }
        __syncthreads();
    }

    // Output: liquid state = exp(pre-reset v2 at step NT-1). Disjoint ranges.
    float* ob = out + (size_t)b * 128;
    if (roleB) {
        float2 o2; o2.x = expf(pcx); o2.y = expf(pcy);
        reinterpret_cast<float2*>(ob)[lane] = o2;        // neurons 2l, 2l+1
        ob[64 + lane] = expf(pcz);                       // neuron 64+l
    } else {
        ob[96 + lane] = expf(pcw);                       // neuron 96+l
    }
}

extern "C" void kernel_launch(void* const* d_in, const int* in_sizes, int n_in,
                              void* d_out, int out_size) {
    const float* x  = (const float*)d_in[0];
    const float* W1 = (const float*)d_in[1];
    const float* W2 = (const float*)d_in[2];
    float* out = (float*)d_out;

    prep_kernel<<<1, 256>>>(W1, W2);
    lsm_kernel<<<NB / 2, 128>>>(x, out);
}